// round 1
// baseline (speedup 1.0000x reference)
#include <cuda_runtime.h>
#include <math.h>

#define N_PATCH 676
#define N_PAD   768
#define DIM     384
#define M_LIB   200000
#define IMG     224
#define KS      33
#define RAD     16
#define SIGMA   4.0f

#define BM 128
#define BN 128
#define BK 8
#define TM 8
#define TN 8

// ---------------- scratch (device globals: no allocation allowed) ----------------
__device__ __align__(16) float g_patch_n[N_PAD * DIM];
__device__ float g_pn[N_PAD];
__device__ float g_ln[M_LIB];
__device__ unsigned long long g_minkey[N_PATCH];
__device__ float g_map26[N_PATCH];
__device__ int   g_sidx;
__device__ float g_sstar;
__device__ int   g_mstar_idx;
__device__ __align__(16) float g_mstar[DIM];
__device__ __align__(16) float g_mtest[DIM];
__device__ float g_msn;
__device__ float g_dstar[M_LIB];
__device__ unsigned long long g_top5[5];
__device__ float g_resized[IMG * IMG];
__device__ float g_tmp[IMG * IMG];
__device__ float g_gw[KS];

__device__ __forceinline__ unsigned long long ullmin_(unsigned long long a, unsigned long long b) {
    return a < b ? a : b;
}
__device__ __forceinline__ unsigned long long ullmax_(unsigned long long a, unsigned long long b) {
    return a > b ? a : b;
}

// ---------------- init: minkeys, zero padding, gaussian weights ----------------
__global__ void k_init() {
    int t = threadIdx.x;
    for (int i = t; i < N_PATCH; i += 256) g_minkey[i] = ~0ull;
    for (int i = t; i < (N_PAD - N_PATCH); i += 256) g_pn[N_PATCH + i] = 0.f;
    for (int i = t; i < (N_PAD - N_PATCH) * DIM; i += 256) g_patch_n[N_PATCH * DIM + i] = 0.f;
    if (t == 0) {
        float w[KS]; float s = 0.f;
        for (int i = 0; i < KS; i++) {
            float x = (float)(i - RAD);
            w[i] = expf(-0.5f * (x / SIGMA) * (x / SIGMA));
            s += w[i];
        }
        for (int i = 0; i < KS; i++) g_gw[i] = w[i] / s;
    }
}

// ---------------- normalize patch rows, compute pn ----------------
__global__ void k_normalize(const float* __restrict__ patch) {
    __shared__ float red[128];
    int n = blockIdx.x;
    int t = threadIdx.x;
    float s = 0.f;
    for (int i = t; i < DIM; i += 128) {
        float v = patch[n * DIM + i];
        s += v * v;
    }
    red[t] = s; __syncthreads();
    for (int o = 64; o > 0; o >>= 1) {
        if (t < o) red[t] += red[t + o];
        __syncthreads();
    }
    float s2 = red[0];
    float nm = sqrtf(s2);
    float inv = 1.0f / fmaxf(nm, 1e-12f);
    for (int i = t; i < DIM; i += 128) g_patch_n[n * DIM + i] = patch[n * DIM + i] * inv;
    if (t == 0) g_pn[n] = s2 * inv * inv;
}

// ---------------- per-lib-row squared norms (warp per row) ----------------
__global__ void k_ln(const float* __restrict__ lib) {
    int w = (blockIdx.x * blockDim.x + threadIdx.x) >> 5;
    int lane = threadIdx.x & 31;
    if (w >= M_LIB) return;
    const float* row = lib + (size_t)w * DIM;
    float s = 0.f;
#pragma unroll
    for (int i = 0; i < DIM / 32; i++) {
        float v = row[lane + 32 * i];
        s += v * v;
    }
#pragma unroll
    for (int o = 16; o > 0; o >>= 1) s += __shfl_down_sync(0xffffffffu, s, o);
    if (lane == 0) g_ln[w] = s;
}

// ---------------- fused GEMM + per-patch-column min(dist, idx) ----------------
__global__ void __launch_bounds__(256) k_gemm_min(const float* __restrict__ lib) {
    __shared__ __align__(16) float As[BK][BM];   // lib tile (k-major)
    __shared__ __align__(16) float Bs[BK][BN];   // patch tile (k-major)
    __shared__ unsigned long long red[16][BN];

    int tid = threadIdx.x;
    int tx = tid & 15;
    int ty = tid >> 4;
    int rowBase = blockIdx.x * BM;   // lib rows
    int colBase = blockIdx.y * BN;   // patch rows (columns of C)

    float acc[TM][TN];
#pragma unroll
    for (int r = 0; r < TM; r++)
#pragma unroll
        for (int c = 0; c < TN; c++) acc[r][c] = 0.f;

    int lr = tid >> 1;         // 0..127 row within tile
    int lc = (tid & 1) * 4;    // k offset (0 or 4)

    for (int k0 = 0; k0 < DIM; k0 += BK) {
        float4 av = make_float4(0.f, 0.f, 0.f, 0.f);
        int gr = rowBase + lr;
        if (gr < M_LIB) av = *(const float4*)&lib[(size_t)gr * DIM + k0 + lc];
        As[lc + 0][lr] = av.x; As[lc + 1][lr] = av.y;
        As[lc + 2][lr] = av.z; As[lc + 3][lr] = av.w;

        float4 bv = *(const float4*)&g_patch_n[(colBase + lr) * DIM + k0 + lc];
        Bs[lc + 0][lr] = bv.x; Bs[lc + 1][lr] = bv.y;
        Bs[lc + 2][lr] = bv.z; Bs[lc + 3][lr] = bv.w;
        __syncthreads();

#pragma unroll
        for (int kk = 0; kk < BK; kk++) {
            float4 a0 = *(float4*)&As[kk][ty * TM];
            float4 a1 = *(float4*)&As[kk][ty * TM + 4];
            float4 b0 = *(float4*)&Bs[kk][tx * TN];
            float4 b1 = *(float4*)&Bs[kk][tx * TN + 4];
            float a[TM] = {a0.x, a0.y, a0.z, a0.w, a1.x, a1.y, a1.z, a1.w};
            float b[TN] = {b0.x, b0.y, b0.z, b0.w, b1.x, b1.y, b1.z, b1.w};
#pragma unroll
            for (int r = 0; r < TM; r++)
#pragma unroll
                for (int c = 0; c < TN; c++) acc[r][c] += a[r] * b[c];
        }
        __syncthreads();
    }

    // epilogue: dist = sqrt(max(pn + ln - 2 dot, 0)); key = (distbits<<32)|idx; min
#pragma unroll
    for (int c = 0; c < TN; c++) {
        int jj = colBase + tx * TN + c;
        float pn = g_pn[jj];
        unsigned long long best = ~0ull;
#pragma unroll
        for (int r = 0; r < TM; r++) {
            int i = rowBase + ty * TM + r;
            if (i < M_LIB) {
                float d2 = pn + g_ln[i] - 2.0f * acc[r][c];
                float dist = sqrtf(fmaxf(d2, 0.f));
                unsigned long long key =
                    ((unsigned long long)__float_as_uint(dist) << 32) | (unsigned)i;
                best = ullmin_(best, key);
            }
        }
        red[ty][tx * TN + c] = best;
    }
    __syncthreads();
    if (tid < BN) {
        unsigned long long b = red[0][tid];
#pragma unroll
        for (int q = 1; q < 16; q++) b = ullmin_(b, red[q][tid]);
        int jj = colBase + tid;
        if (jj < N_PATCH) atomicMin(&g_minkey[jj], b);
    }
}

// ---------------- argmax over min_val (first-index tie-break), fill map26 ----------------
__global__ void k_argmax() {
    __shared__ unsigned long long red[1024];
    int t = threadIdx.x;
    unsigned long long key = 0ull;
    if (t < N_PATCH) {
        unsigned long long mk = g_minkey[t];
        unsigned db = (unsigned)(mk >> 32);
        g_map26[t] = __uint_as_float(db);
        key = ((unsigned long long)db << 32) | (unsigned long long)(0xFFFFFFFFu - (unsigned)t);
    }
    red[t] = key; __syncthreads();
    for (int o = 512; o > 0; o >>= 1) {
        if (t < o) red[t] = ullmax_(red[t], red[t + o]);
        __syncthreads();
    }
    if (t == 0) {
        unsigned long long k = red[0];
        int sidx = (int)(0xFFFFFFFFu - (unsigned)(k & 0xFFFFFFFFull));
        g_sidx = sidx;
        g_sstar = __uint_as_float((unsigned)(k >> 32));
        g_mstar_idx = (int)(unsigned)(g_minkey[sidx] & 0xFFFFFFFFull);
    }
}

// ---------------- gather m_star / m_test_star, msn = ||m_star||^2 ----------------
__global__ void k_prep(const float* __restrict__ lib) {
    __shared__ float part[12];
    int t = threadIdx.x;   // 384
    int lane = t & 31, w = t >> 5;
    float mv = lib[(size_t)g_mstar_idx * DIM + t];
    g_mstar[t] = mv;
    g_mtest[t] = g_patch_n[g_sidx * DIM + t];
    float s = mv * mv;
#pragma unroll
    for (int o = 16; o > 0; o >>= 1) s += __shfl_down_sync(0xffffffffu, s, o);
    if (lane == 0) part[w] = s;
    __syncthreads();
    if (t == 0) {
        float tot = 0.f;
        for (int q = 0; q < 12; q++) tot += part[q];
        g_msn = tot;
    }
}

// ---------------- d_star over the lib (warp per row) ----------------
__global__ void k_dstar(const float* __restrict__ lib) {
    int w = (blockIdx.x * blockDim.x + threadIdx.x) >> 5;
    int lane = threadIdx.x & 31;
    if (w >= M_LIB) return;
    const float* row = lib + (size_t)w * DIM;
    float s = 0.f;
#pragma unroll
    for (int i = 0; i < DIM / 32; i++) s += row[lane + 32 * i] * g_mstar[lane + 32 * i];
#pragma unroll
    for (int o = 16; o > 0; o >>= 1) s += __shfl_down_sync(0xffffffffu, s, o);
    if (lane == 0) {
        float d2 = g_ln[w] + g_msn - 2.0f * s;
        g_dstar[w] = sqrtf(fmaxf(d2, 0.f));
    }
}

// ---------------- top-5 smallest d_star (stable: (distbits<<32)|idx) ----------------
__global__ void k_top5() {
    __shared__ unsigned long long s5[1024 * 5];
    int t = threadIdx.x;
    unsigned long long loc[5] = {~0ull, ~0ull, ~0ull, ~0ull, ~0ull};
    for (int m = t; m < M_LIB; m += 1024) {
        unsigned long long key =
            ((unsigned long long)__float_as_uint(g_dstar[m]) << 32) | (unsigned)m;
        if (key < loc[4]) {
            int p = 4;
            while (p > 0 && key < loc[p - 1]) { loc[p] = loc[p - 1]; p--; }
            loc[p] = key;
        }
    }
#pragma unroll
    for (int q = 0; q < 5; q++) s5[t * 5 + q] = loc[q];
    for (int off = 512; off >= 1; off >>= 1) {
        __syncthreads();
        if (t < off) {
            unsigned long long a[5], b[5], r[5];
#pragma unroll
            for (int q = 0; q < 5; q++) { a[q] = s5[t * 5 + q]; b[q] = s5[(t + off) * 5 + q]; }
            int i = 0, j = 0;
#pragma unroll
            for (int q = 0; q < 5; q++) r[q] = (a[i] <= b[j]) ? a[i++] : b[j++];
#pragma unroll
            for (int q = 0; q < 5; q++) s5[t * 5 + q] = r[q];
        }
    }
    __syncthreads();
    if (t == 0)
        for (int q = 0; q < 5; q++) g_top5[q] = s5[q];
}

// ---------------- final scalar s ----------------
__global__ void k_score(const float* __restrict__ lib, float* __restrict__ out) {
    __shared__ float nbsq[6];
    int t = threadIdx.x;       // 192 = 6 warps
    int w = t >> 5, lane = t & 31;
    const float* vec;
    if (w < 5) vec = lib + (size_t)(unsigned)(g_top5[w] & 0xFFFFFFFFull) * DIM;
    else       vec = g_mstar;
    float s = 0.f;
#pragma unroll
    for (int i = 0; i < DIM / 32; i++) {
        float d = g_mtest[lane + 32 * i] - vec[lane + 32 * i];
        s += d * d;
    }
#pragma unroll
    for (int o = 16; o > 0; o >>= 1) s += __shfl_down_sync(0xffffffffu, s, o);
    if (lane == 0) nbsq[w] = s;
    __syncthreads();
    if (t == 0) {
        float denom = 0.f;
        for (int q = 0; q < 5; q++) denom += expf(sqrtf(nbsq[q]));
        float numer = expf(sqrtf(nbsq[5]));
        out[0] = (1.0f - numer / denom) * g_sstar;
    }
}

// ---------------- bilinear resize 26->224 (half-pixel, clamp == jax linear) ----------------
__global__ void k_resize() {
    int idx = blockIdx.x * blockDim.x + threadIdx.x;
    if (idx >= IMG * IMG) return;
    int x = idx % IMG, y = idx / IMG;
    const float sc = 26.0f / 224.0f;
    float sx = (x + 0.5f) * sc - 0.5f;
    float sy = (y + 0.5f) * sc - 0.5f;
    int x0 = (int)floorf(sx);
    int y0 = (int)floorf(sy);
    float wx = sx - (float)x0;
    float wy = sy - (float)y0;
    int x0c = min(max(x0, 0), 25), x1c = min(max(x0 + 1, 0), 25);
    int y0c = min(max(y0, 0), 25), y1c = min(max(y0 + 1, 0), 25);
    float v00 = g_map26[y0c * 26 + x0c], v01 = g_map26[y0c * 26 + x1c];
    float v10 = g_map26[y1c * 26 + x0c], v11 = g_map26[y1c * 26 + x1c];
    g_resized[idx] = (1.f - wy) * ((1.f - wx) * v00 + wx * v01)
                   + wy * ((1.f - wx) * v10 + wx * v11);
}

__device__ __forceinline__ int reflect_(int i) {
    if (i < 0) return -i;
    if (i >= IMG) return 2 * IMG - 2 - i;
    return i;
}

__global__ void k_blur_v() {
    int idx = blockIdx.x * blockDim.x + threadIdx.x;
    if (idx >= IMG * IMG) return;
    int x = idx % IMG, y = idx / IMG;
    float s = 0.f;
#pragma unroll
    for (int t = 0; t < KS; t++) {
        int yy = reflect_(y + t - RAD);
        s += g_gw[t] * g_resized[yy * IMG + x];
    }
    g_tmp[idx] = s;
}

__global__ void k_blur_h(float* __restrict__ out) {
    int idx = blockIdx.x * blockDim.x + threadIdx.x;
    if (idx >= IMG * IMG) return;
    int x = idx % IMG, y = idx / IMG;
    float s = 0.f;
#pragma unroll
    for (int t = 0; t < KS; t++) {
        int xx = reflect_(x + t - RAD);
        s += g_gw[t] * g_tmp[y * IMG + xx];
    }
    out[1 + idx] = s;
}

// ---------------- launch ----------------
extern "C" void kernel_launch(void* const* d_in, const int* in_sizes, int n_in,
                              void* d_out, int out_size) {
    const float* patch = (const float*)d_in[0];
    const float* lib   = (const float*)d_in[1];
    if (n_in >= 2 && in_sizes[0] > in_sizes[1]) {  // defensive: patch is the small one
        const float* t = patch; patch = lib; lib = t;
    }
    float* out = (float*)d_out;

    k_init<<<1, 256>>>();
    k_normalize<<<N_PATCH, 128>>>(patch);
    k_ln<<<(M_LIB * 32 + 255) / 256, 256>>>(lib);

    dim3 grid((M_LIB + BM - 1) / BM, (N_PAD + BN - 1) / BN);
    k_gemm_min<<<grid, 256>>>(lib);

    k_argmax<<<1, 1024>>>();
    k_prep<<<1, DIM>>>(lib);
    k_dstar<<<(M_LIB * 32 + 255) / 256, 256>>>(lib);
    k_top5<<<1, 1024>>>();
    k_score<<<1, 192>>>(lib, out);

    int px = IMG * IMG;
    k_resize<<<(px + 255) / 256, 256>>>();
    k_blur_v<<<(px + 255) / 256, 256>>>();
    k_blur_h<<<(px + 255) / 256, 256>>>(out);
}

// round 9
// speedup vs baseline: 2.1320x; 2.1320x over previous
#include <cuda_runtime.h>
#include <cuda_bf16.h>
#include <math.h>
#include <stdint.h>

#define N_PATCH 676
#define N_PAD   768
#define DIM     384
#define M_LIB   200000
#define IMG     224
#define KS      33
#define RAD     16
#define SIGMA   4.0f

// ---------------- mma.sync GEMM tiling ----------------
#define TM_CTA 128                      // patch rows per CTA
#define TN_CTA 128                      // lib rows per CTA
#define KC     64                       // K per chunk
#define NCHUNK (DIM / KC)               // 6
#define NT_PATCH (N_PAD / TM_CTA)       // 6
#define NT_LIB  ((M_LIB + TN_CTA - 1) / TN_CTA)  // 1563

// smem word layout (u32 words), padded row stride 36 words = 72 bf16
#define WSTR  36
#define A_H_OFF 0
#define A_L_OFF (128 * WSTR)
#define B_H_OFF (2 * 128 * WSTR)
#define B_L_OFF (3 * 128 * WSTR)
#define BUF_WORDS (4 * 128 * WSTR)            // 18432 words = 73728 B
#define LN_OFF_B  (BUF_WORDS * 4)             // bytes
#define RED_OFF_B (LN_OFF_B + 512)
#define SMEM_TOTAL_B (RED_OFF_B + 128 * 2 * 8)  // 76288 B

typedef unsigned long long ull;

__device__ __forceinline__ ull ullmin_(ull a, ull b) { return a < b ? a : b; }
__device__ __forceinline__ ull ullmax_(ull a, ull b) { return a > b ? a : b; }

__device__ __forceinline__ void mma16816(float* c, const uint32_t* a, const uint32_t* b) {
    asm volatile(
        "mma.sync.aligned.m16n8k16.row.col.f32.bf16.bf16.f32 "
        "{%0,%1,%2,%3}, {%4,%5,%6,%7}, {%8,%9}, {%0,%1,%2,%3};"
        : "+f"(c[0]), "+f"(c[1]), "+f"(c[2]), "+f"(c[3])
        : "r"(a[0]), "r"(a[1]), "r"(a[2]), "r"(a[3]), "r"(b[0]), "r"(b[1]));
}

__device__ __forceinline__ void split2(float x0, float x1, uint32_t& h, uint32_t& l) {
    __nv_bfloat16 h0 = __float2bfloat16_rn(x0), h1 = __float2bfloat16_rn(x1);
    float f0 = __bfloat162float(h0), f1 = __bfloat162float(h1);
    __nv_bfloat16 l0 = __float2bfloat16_rn(x0 - f0), l1 = __float2bfloat16_rn(x1 - f1);
    h = ((uint32_t)__bfloat16_as_ushort(h1) << 16) | (uint32_t)__bfloat16_as_ushort(h0);
    l = ((uint32_t)__bfloat16_as_ushort(l1) << 16) | (uint32_t)__bfloat16_as_ushort(l0);
}

// ---------------- scratch (device globals) ----------------
__device__ __align__(16) float g_patch_n[N_PAD * DIM];
__device__ float g_pn[N_PAD];
__device__ float g_ln[M_LIB];
__device__ ull   g_minkey[N_PATCH];
__device__ float g_map26[N_PATCH];
__device__ int   g_sidx;
__device__ float g_sstar;
__device__ int   g_mstar_idx;
__device__ __align__(16) float g_mstar[DIM];
__device__ __align__(16) float g_mtest[DIM];
__device__ float g_msn;
__device__ float g_dstar[M_LIB];
__device__ ull   g_top5[5];
__device__ float g_resized[IMG * IMG];
__device__ float g_tmp[IMG * IMG];
__device__ float g_gw[KS];

// ---------------- init ----------------
__global__ void k_init() {
    int t = threadIdx.x;
    for (int i = t; i < N_PATCH; i += 256) g_minkey[i] = ~0ull;
    for (int i = t; i < (N_PAD - N_PATCH); i += 256) g_pn[N_PATCH + i] = 0.f;
    for (int i = t; i < (N_PAD - N_PATCH) * DIM; i += 256) g_patch_n[N_PATCH * DIM + i] = 0.f;
    if (t == 0) {
        float w[KS]; float s = 0.f;
        for (int i = 0; i < KS; i++) {
            float x = (float)(i - RAD);
            w[i] = expf(-0.5f * (x / SIGMA) * (x / SIGMA));
            s += w[i];
        }
        for (int i = 0; i < KS; i++) g_gw[i] = w[i] / s;
    }
}

// ---------------- normalize patch rows ----------------
__global__ void k_normalize(const float* __restrict__ patch) {
    __shared__ float red[128];
    int n = blockIdx.x, t = threadIdx.x;
    float s = 0.f;
    for (int i = t; i < DIM; i += 128) { float v = patch[n * DIM + i]; s += v * v; }
    red[t] = s; __syncthreads();
    for (int o = 64; o > 0; o >>= 1) { if (t < o) red[t] += red[t + o]; __syncthreads(); }
    float s2 = red[0];
    float inv = 1.0f / fmaxf(sqrtf(s2), 1e-12f);
    for (int i = t; i < DIM; i += 128) g_patch_n[n * DIM + i] = patch[n * DIM + i] * inv;
    if (t == 0) g_pn[n] = s2 * inv * inv;
}

// ---------------- lib row squared norms ----------------
__global__ void k_ln(const float* __restrict__ lib) {
    int w = (blockIdx.x * blockDim.x + threadIdx.x) >> 5;
    int lane = threadIdx.x & 31;
    if (w >= M_LIB) return;
    const float* row = lib + (size_t)w * DIM;
    float s = 0.f;
#pragma unroll
    for (int i = 0; i < DIM / 32; i++) { float v = row[lane + 32 * i]; s += v * v; }
#pragma unroll
    for (int o = 16; o > 0; o >>= 1) s += __shfl_down_sync(0xffffffffu, s, o);
    if (lane == 0) g_ln[w] = s;
}

// ---------------- bf16x3 mma.sync GEMM + fused per-patch min ----------------
__global__ void __launch_bounds__(256, 2) k_gemm_mma(const float* __restrict__ lib) {
    extern __shared__ __align__(16) char smem[];
    uint32_t* sw = (uint32_t*)smem;
    float* ln_s = (float*)(smem + LN_OFF_B);
    ull (*red)[2] = (ull (*)[2])(smem + RED_OFF_B);

    int tid = threadIdx.x;
    int lane = tid & 31, w = tid >> 5;
    int wm = w & 3, wn = w >> 2;       // 4 m-warps x 2 n-warps
    int gid = lane >> 2, t4 = lane & 3;
    int mBase = blockIdx.x * TM_CTA;   // patch rows
    int nBase = blockIdx.y * TN_CTA;   // lib rows

    // stage ln tile (covered by first __syncthreads)
    if (tid < 128) {
        int g = nBase + tid;
        ln_s[tid] = (g < M_LIB) ? g_ln[g] : 0.f;
    }

    float c[2][8][4];
#pragma unroll
    for (int mt = 0; mt < 2; mt++)
#pragma unroll
        for (int nt = 0; nt < 8; nt++)
#pragma unroll
            for (int q = 0; q < 4; q++) c[mt][nt][q] = 0.f;

    for (int ch = 0; ch < NCHUNK; ch++) {
        int k0 = ch * KC;
        // ---- fill A (patch, always valid thanks to padding) ----
#pragma unroll
        for (int it = 0; it < 8; it++) {
            int idx = tid + it * 256;
            int row = idx >> 4, q = idx & 15;       // q: float4 index within 64 floats
            float4 v = *(const float4*)&g_patch_n[(mBase + row) * DIM + k0 + q * 4];
            uint32_t h01, l01, h23, l23;
            split2(v.x, v.y, h01, l01);
            split2(v.z, v.w, h23, l23);
            int base = row * WSTR + q * 2;
            sw[A_H_OFF + base] = h01; sw[A_H_OFF + base + 1] = h23;
            sw[A_L_OFF + base] = l01; sw[A_L_OFF + base + 1] = l23;
        }
        // ---- fill B (lib, guard tail) ----
#pragma unroll
        for (int it = 0; it < 8; it++) {
            int idx = tid + it * 256;
            int row = idx >> 4, q = idx & 15;
            int gr = nBase + row;
            float4 v = (gr < M_LIB) ? *(const float4*)&lib[(size_t)gr * DIM + k0 + q * 4]
                                    : make_float4(0.f, 0.f, 0.f, 0.f);
            uint32_t h01, l01, h23, l23;
            split2(v.x, v.y, h01, l01);
            split2(v.z, v.w, h23, l23);
            int base = row * WSTR + q * 2;
            sw[B_H_OFF + base] = h01; sw[B_H_OFF + base + 1] = h23;
            sw[B_L_OFF + base] = l01; sw[B_L_OFF + base + 1] = l23;
        }
        __syncthreads();

#pragma unroll
        for (int ks = 0; ks < KC / 16; ks++) {
            uint32_t ah[2][4], al[2][4];
#pragma unroll
            for (int mt = 0; mt < 2; mt++) {
                int r0 = (wm * 32 + mt * 16 + gid) * WSTR + ks * 8;
                int r1 = r0 + 8 * WSTR;
                ah[mt][0] = sw[A_H_OFF + r0 + t4];
                ah[mt][1] = sw[A_H_OFF + r1 + t4];
                ah[mt][2] = sw[A_H_OFF + r0 + 4 + t4];
                ah[mt][3] = sw[A_H_OFF + r1 + 4 + t4];
                al[mt][0] = sw[A_L_OFF + r0 + t4];
                al[mt][1] = sw[A_L_OFF + r1 + t4];
                al[mt][2] = sw[A_L_OFF + r0 + 4 + t4];
                al[mt][3] = sw[A_L_OFF + r1 + 4 + t4];
            }
#pragma unroll
            for (int nt = 0; nt < 8; nt++) {
                int cb = (wn * 64 + nt * 8 + gid) * WSTR + ks * 8;
                uint32_t bh[2], bl[2];
                bh[0] = sw[B_H_OFF + cb + t4];
                bh[1] = sw[B_H_OFF + cb + 4 + t4];
                bl[0] = sw[B_L_OFF + cb + t4];
                bl[1] = sw[B_L_OFF + cb + 4 + t4];
#pragma unroll
                for (int mt = 0; mt < 2; mt++) {
                    mma16816(c[mt][nt], ah[mt], bh);
                    mma16816(c[mt][nt], ah[mt], bl);
                    mma16816(c[mt][nt], al[mt], bh);
                }
            }
        }
        __syncthreads();
    }

    // ---- epilogue: dist + min over lib cols ----
    bool fullTile = (nBase + TN_CTA <= M_LIB);
#pragma unroll
    for (int mt = 0; mt < 2; mt++) {
#pragma unroll
        for (int half = 0; half < 2; half++) {
            int rloc = wm * 32 + mt * 16 + gid + 8 * half;
            float pn = g_pn[mBase + rloc];
            ull best = ~0ull;
#pragma unroll
            for (int nt = 0; nt < 8; nt++) {
#pragma unroll
                for (int cc = 0; cc < 2; cc++) {
                    int cloc = wn * 64 + nt * 8 + t4 * 2 + cc;
                    int gcol = nBase + cloc;
                    if (fullTile || gcol < M_LIB) {
                        float dot = c[mt][nt][half * 2 + cc];
                        float d2 = pn + ln_s[cloc] - 2.0f * dot;
                        float dist = sqrtf(fmaxf(d2, 0.f));
                        ull key = ((ull)__float_as_uint(dist) << 32) | (unsigned)gcol;
                        best = ullmin_(best, key);
                    }
                }
            }
            best = ullmin_(best, __shfl_xor_sync(0xffffffffu, best, 1));
            best = ullmin_(best, __shfl_xor_sync(0xffffffffu, best, 2));
            if (t4 == 0) red[rloc][wn] = best;
        }
    }
    __syncthreads();
    if (tid < 128) {
        ull b = ullmin_(red[tid][0], red[tid][1]);
        int prow = mBase + tid;
        if (prow < N_PATCH) atomicMin(&g_minkey[prow], b);
    }
}

// ---------------- argmax over min_val ----------------
__global__ void k_argmax() {
    __shared__ ull red[1024];
    int t = threadIdx.x;
    ull key = 0ull;
    if (t < N_PATCH) {
        ull mk = g_minkey[t];
        unsigned db = (unsigned)(mk >> 32);
        g_map26[t] = __uint_as_float(db);
        key = ((ull)db << 32) | (ull)(0xFFFFFFFFu - (unsigned)t);
    }
    red[t] = key; __syncthreads();
    for (int o = 512; o > 0; o >>= 1) { if (t < o) red[t] = ullmax_(red[t], red[t + o]); __syncthreads(); }
    if (t == 0) {
        ull k = red[0];
        int sidx = (int)(0xFFFFFFFFu - (unsigned)(k & 0xFFFFFFFFull));
        g_sidx = sidx;
        g_sstar = __uint_as_float((unsigned)(k >> 32));
        g_mstar_idx = (int)(unsigned)(g_minkey[sidx] & 0xFFFFFFFFull);
    }
}

__global__ void k_prep(const float* __restrict__ lib) {
    __shared__ float part[12];
    int t = threadIdx.x;
    int lane = t & 31, w = t >> 5;
    float mv = lib[(size_t)g_mstar_idx * DIM + t];
    g_mstar[t] = mv;
    g_mtest[t] = g_patch_n[g_sidx * DIM + t];
    float s = mv * mv;
#pragma unroll
    for (int o = 16; o > 0; o >>= 1) s += __shfl_down_sync(0xffffffffu, s, o);
    if (lane == 0) part[w] = s;
    __syncthreads();
    if (t == 0) { float tot = 0.f; for (int q = 0; q < 12; q++) tot += part[q]; g_msn = tot; }
}

__global__ void k_dstar(const float* __restrict__ lib) {
    int w = (blockIdx.x * blockDim.x + threadIdx.x) >> 5;
    int lane = threadIdx.x & 31;
    if (w >= M_LIB) return;
    const float* row = lib + (size_t)w * DIM;
    float s = 0.f;
#pragma unroll
    for (int i = 0; i < DIM / 32; i++) s += row[lane + 32 * i] * g_mstar[lane + 32 * i];
#pragma unroll
    for (int o = 16; o > 0; o >>= 1) s += __shfl_down_sync(0xffffffffu, s, o);
    if (lane == 0) {
        float d2 = g_ln[w] + g_msn - 2.0f * s;
        g_dstar[w] = sqrtf(fmaxf(d2, 0.f));
    }
}

__global__ void k_top5() {
    __shared__ ull s5[1024 * 5];
    int t = threadIdx.x;
    ull loc[5] = {~0ull, ~0ull, ~0ull, ~0ull, ~0ull};
    for (int m = t; m < M_LIB; m += 1024) {
        ull key = ((ull)__float_as_uint(g_dstar[m]) << 32) | (unsigned)m;
        if (key < loc[4]) {
            int p = 4;
            while (p > 0 && key < loc[p - 1]) { loc[p] = loc[p - 1]; p--; }
            loc[p] = key;
        }
    }
#pragma unroll
    for (int q = 0; q < 5; q++) s5[t * 5 + q] = loc[q];
    for (int off = 512; off >= 1; off >>= 1) {
        __syncthreads();
        if (t < off) {
            ull a[5], b[5], r[5];
#pragma unroll
            for (int q = 0; q < 5; q++) { a[q] = s5[t * 5 + q]; b[q] = s5[(t + off) * 5 + q]; }
            int i = 0, j = 0;
#pragma unroll
            for (int q = 0; q < 5; q++) r[q] = (a[i] <= b[j]) ? a[i++] : b[j++];
#pragma unroll
            for (int q = 0; q < 5; q++) s5[t * 5 + q] = r[q];
        }
    }
    __syncthreads();
    if (t == 0) for (int q = 0; q < 5; q++) g_top5[q] = s5[q];
}

__global__ void k_score(const float* __restrict__ lib, float* __restrict__ out) {
    __shared__ float nbsq[6];
    int t = threadIdx.x;
    int w = t >> 5, lane = t & 31;
    const float* vec;
    if (w < 5) vec = lib + (size_t)(unsigned)(g_top5[w] & 0xFFFFFFFFull) * DIM;
    else       vec = g_mstar;
    float s = 0.f;
#pragma unroll
    for (int i = 0; i < DIM / 32; i++) {
        float d = g_mtest[lane + 32 * i] - vec[lane + 32 * i];
        s += d * d;
    }
#pragma unroll
    for (int o = 16; o > 0; o >>= 1) s += __shfl_down_sync(0xffffffffu, s, o);
    if (lane == 0) nbsq[w] = s;
    __syncthreads();
    if (t == 0) {
        float denom = 0.f;
        for (int q = 0; q < 5; q++) denom += expf(sqrtf(nbsq[q]));
        float numer = expf(sqrtf(nbsq[5]));
        out[0] = (1.0f - numer / denom) * g_sstar;
    }
}

// ---------------- resize + blur ----------------
__global__ void k_resize() {
    int idx = blockIdx.x * blockDim.x + threadIdx.x;
    if (idx >= IMG * IMG) return;
    int x = idx % IMG, y = idx / IMG;
    const float sc = 26.0f / 224.0f;
    float sx = (x + 0.5f) * sc - 0.5f;
    float sy = (y + 0.5f) * sc - 0.5f;
    int x0 = (int)floorf(sx), y0 = (int)floorf(sy);
    float wx = sx - (float)x0, wy = sy - (float)y0;
    int x0c = min(max(x0, 0), 25), x1c = min(max(x0 + 1, 0), 25);
    int y0c = min(max(y0, 0), 25), y1c = min(max(y0 + 1, 0), 25);
    float v00 = g_map26[y0c * 26 + x0c], v01 = g_map26[y0c * 26 + x1c];
    float v10 = g_map26[y1c * 26 + x0c], v11 = g_map26[y1c * 26 + x1c];
    g_resized[idx] = (1.f - wy) * ((1.f - wx) * v00 + wx * v01) + wy * ((1.f - wx) * v10 + wx * v11);
}

__device__ __forceinline__ int reflect_(int i) {
    if (i < 0) return -i;
    if (i >= IMG) return 2 * IMG - 2 - i;
    return i;
}

__global__ void k_blur_v() {
    int idx = blockIdx.x * blockDim.x + threadIdx.x;
    if (idx >= IMG * IMG) return;
    int x = idx % IMG, y = idx / IMG;
    float s = 0.f;
#pragma unroll
    for (int t = 0; t < KS; t++) { int yy = reflect_(y + t - RAD); s += g_gw[t] * g_resized[yy * IMG + x]; }
    g_tmp[idx] = s;
}

__global__ void k_blur_h(float* __restrict__ out) {
    int idx = blockIdx.x * blockDim.x + threadIdx.x;
    if (idx >= IMG * IMG) return;
    int x = idx % IMG, y = idx / IMG;
    float s = 0.f;
#pragma unroll
    for (int t = 0; t < KS; t++) { int xx = reflect_(x + t - RAD); s += g_gw[t] * g_tmp[y * IMG + xx]; }
    out[1 + idx] = s;
}

// ---------------- launch ----------------
extern "C" void kernel_launch(void* const* d_in, const int* in_sizes, int n_in,
                              void* d_out, int out_size) {
    const float* patch = (const float*)d_in[0];
    const float* lib   = (const float*)d_in[1];
    if (n_in >= 2 && in_sizes[0] > in_sizes[1]) {
        const float* t = patch; patch = lib; lib = t;
    }
    float* out = (float*)d_out;

    cudaFuncSetAttribute(k_gemm_mma, cudaFuncAttributeMaxDynamicSharedMemorySize, SMEM_TOTAL_B);

    k_init<<<1, 256>>>();
    k_normalize<<<N_PATCH, 128>>>(patch);
    k_ln<<<(M_LIB * 32 + 255) / 256, 256>>>(lib);

    dim3 grid(NT_PATCH, NT_LIB);   // patch tiles fastest -> lib tile L2 reuse
    k_gemm_mma<<<grid, 256, SMEM_TOTAL_B>>>(lib);

    k_argmax<<<1, 1024>>>();
    k_prep<<<1, DIM>>>(lib);
    k_dstar<<<(M_LIB * 32 + 255) / 256, 256>>>(lib);
    k_top5<<<1, 1024>>>();
    k_score<<<1, 192>>>(lib, out);

    int px = IMG * IMG;
    k_resize<<<(px + 255) / 256, 256>>>();
    k_blur_v<<<(px + 255) / 256, 256>>>();
    k_blur_h<<<(px + 255) / 256, 256>>>(out);
}

// round 13
// speedup vs baseline: 2.4787x; 1.1627x over previous
#include <cuda_runtime.h>
#include <cuda_bf16.h>
#include <math.h>
#include <stdint.h>

#define N_PATCH 676
#define N_PAD   768
#define DIM     384
#define M_LIB   200000
#define IMG     224
#define KS      33
#define RAD     16
#define SIGMA   4.0f

// ---------------- GEMM tiling ----------------
#define TM_CTA 128
#define TN_CTA 128
#define KC     32                       // K per pipeline stage
#define NSTG   (DIM / KC)               // 12
#define NT_PATCH (N_PAD / TM_CTA)       // 6
#define NT_LIB  ((M_LIB + TN_CTA - 1) / TN_CTA)  // 1563

// smem: per stage 4 arrays (Ah, Al, Bh, Bl), each 128 rows x 80B (64B data + 16 pad)
#define ROWB   80
#define ARRB   (128 * ROWB)             // 10240
#define OA_H   0
#define OA_L   ARRB
#define OB_H   (2 * ARRB)
#define OB_L   (3 * ARRB)
#define STB    (4 * ARRB)               // 40960 per stage
#define LN_OFF (2 * STB)                // 81920
#define RED_OFF (LN_OFF + 512)
#define SMEM_TOTAL_B (RED_OFF + 128 * 16)   // 84480

typedef unsigned long long ull;

__device__ __forceinline__ ull ullmin_(ull a, ull b) { return a < b ? a : b; }
__device__ __forceinline__ ull ullmax_(ull a, ull b) { return a > b ? a : b; }

__device__ __forceinline__ uint32_t smem_u32(const void* p) {
    uint32_t a;
    asm("{ .reg .u64 t; cvta.to.shared.u64 t, %1; cvt.u32.u64 %0, t; }" : "=r"(a) : "l"(p));
    return a;
}
__device__ __forceinline__ void mma16816(float* c, const uint32_t* a, const uint32_t* b) {
    asm volatile(
        "mma.sync.aligned.m16n8k16.row.col.f32.bf16.bf16.f32 "
        "{%0,%1,%2,%3}, {%4,%5,%6,%7}, {%8,%9}, {%0,%1,%2,%3};"
        : "+f"(c[0]), "+f"(c[1]), "+f"(c[2]), "+f"(c[3])
        : "r"(a[0]), "r"(a[1]), "r"(a[2]), "r"(a[3]), "r"(b[0]), "r"(b[1]));
}
__device__ __forceinline__ void ldm_x4(uint32_t* r, uint32_t addr) {
    asm volatile("ldmatrix.sync.aligned.m8n8.x4.shared.b16 {%0,%1,%2,%3}, [%4];"
        : "=r"(r[0]), "=r"(r[1]), "=r"(r[2]), "=r"(r[3]) : "r"(addr));
}
__device__ __forceinline__ void cp16(uint32_t dst, const void* src, int ssz) {
    asm volatile("cp.async.ca.shared.global [%0], [%1], 16, %2;"
        :: "r"(dst), "l"(src), "r"(ssz) : "memory");
}
#define CP_COMMIT() asm volatile("cp.async.commit_group;" ::: "memory")
#define CP_WAIT1()  asm volatile("cp.async.wait_group 1;" ::: "memory")
#define CP_WAIT0()  asm volatile("cp.async.wait_group 0;" ::: "memory")

// ---------------- scratch (device globals) ----------------
__device__ __align__(16) float g_patch_n[N_PAD * DIM];
__device__ __align__(16) __nv_bfloat16 g_patch_h[N_PAD * DIM];
__device__ __align__(16) __nv_bfloat16 g_patch_l[N_PAD * DIM];
__device__ __align__(16) __nv_bfloat16 g_lib_h[(size_t)M_LIB * DIM];
__device__ __align__(16) __nv_bfloat16 g_lib_l[(size_t)M_LIB * DIM];
__device__ float g_pn[N_PAD];
__device__ float g_ln[M_LIB];
__device__ ull   g_minkey[N_PATCH];
__device__ float g_map26[N_PATCH];
__device__ int   g_sidx;
__device__ float g_sstar;
__device__ int   g_mstar_idx;
__device__ __align__(16) float g_mstar[DIM];
__device__ __align__(16) float g_mtest[DIM];
__device__ float g_msn;
__device__ float g_dstar[M_LIB];
__device__ ull   g_top5[5];
__device__ float g_resized[IMG * IMG];
__device__ float g_tmp[IMG * IMG];
__device__ float g_gw[KS];

// ---------------- init ----------------
__global__ void k_init() {
    int t = threadIdx.x;
    for (int i = t; i < N_PATCH; i += 256) g_minkey[i] = ~0ull;
    for (int i = t; i < (N_PAD - N_PATCH); i += 256) g_pn[N_PATCH + i] = 0.f;
    __nv_bfloat16 z = __float2bfloat16(0.f);
    for (int i = t; i < (N_PAD - N_PATCH) * DIM; i += 256) {
        g_patch_n[N_PATCH * DIM + i] = 0.f;
        g_patch_h[N_PATCH * DIM + i] = z;
        g_patch_l[N_PATCH * DIM + i] = z;
    }
    if (t == 0) {
        float w[KS]; float s = 0.f;
        for (int i = 0; i < KS; i++) {
            float x = (float)(i - RAD);
            w[i] = expf(-0.5f * (x / SIGMA) * (x / SIGMA));
            s += w[i];
        }
        for (int i = 0; i < KS; i++) g_gw[i] = w[i] / s;
    }
}

// ---------------- normalize patch rows + bf16 split ----------------
__global__ void k_normalize(const float* __restrict__ patch) {
    __shared__ float red[128];
    int n = blockIdx.x, t = threadIdx.x;
    float s = 0.f;
    for (int i = t; i < DIM; i += 128) { float v = patch[n * DIM + i]; s += v * v; }
    red[t] = s; __syncthreads();
    for (int o = 64; o > 0; o >>= 1) { if (t < o) red[t] += red[t + o]; __syncthreads(); }
    float s2 = red[0];
    float inv = 1.0f / fmaxf(sqrtf(s2), 1e-12f);
    for (int i = t; i < DIM; i += 128) {
        float v = patch[n * DIM + i] * inv;
        g_patch_n[n * DIM + i] = v;
        __nv_bfloat16 h = __float2bfloat16_rn(v);
        g_patch_h[n * DIM + i] = h;
        g_patch_l[n * DIM + i] = __float2bfloat16_rn(v - __bfloat162float(h));
    }
    if (t == 0) g_pn[n] = s2 * inv * inv;
}

// ---------------- lib: bf16 hi/lo split + row norms (one pass) ----------------
__global__ void k_split_ln(const float* __restrict__ lib) {
    int w = (blockIdx.x * blockDim.x + threadIdx.x) >> 5;
    int lane = threadIdx.x & 31;
    if (w >= M_LIB) return;
    const float* row = lib + (size_t)w * DIM;
    __nv_bfloat16* rh = g_lib_h + (size_t)w * DIM;
    __nv_bfloat16* rl = g_lib_l + (size_t)w * DIM;
    float s = 0.f;
#pragma unroll
    for (int j = 0; j < 3; j++) {
        int o = lane * 4 + j * 128;
        float4 v = *(const float4*)(row + o);
        s += v.x * v.x + v.y * v.y + v.z * v.z + v.w * v.w;
        __nv_bfloat16 h0 = __float2bfloat16_rn(v.x), h1 = __float2bfloat16_rn(v.y);
        __nv_bfloat16 h2 = __float2bfloat16_rn(v.z), h3 = __float2bfloat16_rn(v.w);
        ushort4 hh, ll;
        hh.x = __bfloat16_as_ushort(h0); hh.y = __bfloat16_as_ushort(h1);
        hh.z = __bfloat16_as_ushort(h2); hh.w = __bfloat16_as_ushort(h3);
        ll.x = __bfloat16_as_ushort(__float2bfloat16_rn(v.x - __bfloat162float(h0)));
        ll.y = __bfloat16_as_ushort(__float2bfloat16_rn(v.y - __bfloat162float(h1)));
        ll.z = __bfloat16_as_ushort(__float2bfloat16_rn(v.z - __bfloat162float(h2)));
        ll.w = __bfloat16_as_ushort(__float2bfloat16_rn(v.w - __bfloat162float(h3)));
        *(ushort4*)(rh + o) = hh;
        *(ushort4*)(rl + o) = ll;
    }
#pragma unroll
    for (int o = 16; o > 0; o >>= 1) s += __shfl_down_sync(0xffffffffu, s, o);
    if (lane == 0) g_ln[w] = s;
}

// ---------------- bf16x3 pipelined mma.sync GEMM + fused per-patch min ----------------
__global__ void __launch_bounds__(256, 2) k_gemm_mma() {
    extern __shared__ __align__(16) char smem[];
    uint32_t sb = smem_u32(smem);
    float* ln_s = (float*)(smem + LN_OFF);
    ull (*red)[2] = (ull (*)[2])(smem + RED_OFF);

    int tid = threadIdx.x;
    int lane = tid & 31, w = tid >> 5;
    int wm = w & 3, wn = w >> 2;
    int gid = lane >> 2, t4 = lane & 3;
    int mBase = blockIdx.x * TM_CTA;
    int nBase = blockIdx.y * TN_CTA;

    if (tid < 128) {
        int g = nBase + tid;
        ln_s[tid] = (g < M_LIB) ? g_ln[g] : 0.f;
    }

    auto fill = [&](int st, int k0) {
        uint32_t base = sb + st * STB;
#pragma unroll
        for (int half = 0; half < 2; half++) {
            int rem = tid + half * 256;          // 0..511
            int row = rem >> 2, ch = rem & 3;
            uint32_t o = (uint32_t)row * ROWB + ch * 16;
            int goff = k0 + ch * 8;
            cp16(base + OA_H + o, g_patch_h + (mBase + row) * DIM + goff, 16);
            cp16(base + OA_L + o, g_patch_l + (mBase + row) * DIM + goff, 16);
            int gr = nBase + row;
            int ssz = (gr < M_LIB) ? 16 : 0;
            size_t bo = (size_t)(ssz ? gr : 0) * DIM + goff;
            cp16(base + OB_H + o, g_lib_h + bo, ssz);
            cp16(base + OB_L + o, g_lib_l + bo, ssz);
        }
    };

    float c[2][8][4];
#pragma unroll
    for (int mt = 0; mt < 2; mt++)
#pragma unroll
        for (int nt = 0; nt < 8; nt++)
#pragma unroll
            for (int q = 0; q < 4; q++) c[mt][nt][q] = 0.f;

    fill(0, 0); CP_COMMIT();
    fill(1, KC); CP_COMMIT();

    for (int s = 0; s < NSTG; s++) {
        if (s >= NSTG - 2) CP_WAIT0(); else CP_WAIT1();
        __syncthreads();
        int buf = s & 1;
        uint32_t base = sb + buf * STB;
#pragma unroll
        for (int ks = 0; ks < KC / 16; ks++) {
            uint32_t ah[2][4], al[2][4];
            int rowA = wm * 32 + (lane & 15);
            uint32_t ka = ks * 32 + ((lane >> 4) & 1) * 16;
#pragma unroll
            for (int mt = 0; mt < 2; mt++) {
                uint32_t ro = (uint32_t)(rowA + mt * 16) * ROWB + ka;
                ldm_x4(ah[mt], base + OA_H + ro);
                ldm_x4(al[mt], base + OA_L + ro);
            }
            int nrow0 = wn * 64 + (lane & 7) + ((lane >> 4) & 1) * 8;
            uint32_t kb = ks * 32 + ((lane >> 3) & 1) * 16;
#pragma unroll
            for (int ntp = 0; ntp < 4; ntp++) {
                uint32_t bh[4], bl[4];
                uint32_t bo = (uint32_t)(nrow0 + ntp * 16) * ROWB + kb;
                ldm_x4(bh, base + OB_H + bo);
                ldm_x4(bl, base + OB_L + bo);
#pragma unroll
                for (int sub = 0; sub < 2; sub++) {
                    int nt = ntp * 2 + sub;
#pragma unroll
                    for (int mt = 0; mt < 2; mt++) {
                        mma16816(c[mt][nt], ah[mt], bh + sub * 2);
                        mma16816(c[mt][nt], ah[mt], bl + sub * 2);
                        mma16816(c[mt][nt], al[mt], bh + sub * 2);
                    }
                }
            }
        }
        __syncthreads();
        if (s + 2 < NSTG) { fill(buf, (s + 2) * KC); CP_COMMIT(); }
    }

    // ---- epilogue: dist + min over lib cols ----
    bool fullTile = (nBase + TN_CTA <= M_LIB);
#pragma unroll
    for (int mt = 0; mt < 2; mt++) {
#pragma unroll
        for (int half = 0; half < 2; half++) {
            int rloc = wm * 32 + mt * 16 + gid + 8 * half;
            float pn = g_pn[mBase + rloc];
            ull best = ~0ull;
#pragma unroll
            for (int nt = 0; nt < 8; nt++) {
#pragma unroll
                for (int cc = 0; cc < 2; cc++) {
                    int cloc = wn * 64 + nt * 8 + t4 * 2 + cc;
                    int gcol = nBase + cloc;
                    if (fullTile || gcol < M_LIB) {
                        float dot = c[mt][nt][half * 2 + cc];
                        float d2 = pn + ln_s[cloc] - 2.0f * dot;
                        float dist = sqrtf(fmaxf(d2, 0.f));
                        ull key = ((ull)__float_as_uint(dist) << 32) | (unsigned)gcol;
                        best = ullmin_(best, key);
                    }
                }
            }
            best = ullmin_(best, __shfl_xor_sync(0xffffffffu, best, 1));
            best = ullmin_(best, __shfl_xor_sync(0xffffffffu, best, 2));
            if (t4 == 0) red[rloc][wn] = best;
        }
    }
    __syncthreads();
    if (tid < 128) {
        ull b = ullmin_(red[tid][0], red[tid][1]);
        int prow = mBase + tid;
        if (prow < N_PATCH) atomicMin(&g_minkey[prow], b);
    }
}

// ---------------- argmax over min_val ----------------
__global__ void k_argmax() {
    __shared__ ull red[1024];
    int t = threadIdx.x;
    ull key = 0ull;
    if (t < N_PATCH) {
        ull mk = g_minkey[t];
        unsigned db = (unsigned)(mk >> 32);
        g_map26[t] = __uint_as_float(db);
        key = ((ull)db << 32) | (ull)(0xFFFFFFFFu - (unsigned)t);
    }
    red[t] = key; __syncthreads();
    for (int o = 512; o > 0; o >>= 1) { if (t < o) red[t] = ullmax_(red[t], red[t + o]); __syncthreads(); }
    if (t == 0) {
        ull k = red[0];
        int sidx = (int)(0xFFFFFFFFu - (unsigned)(k & 0xFFFFFFFFull));
        g_sidx = sidx;
        g_sstar = __uint_as_float((unsigned)(k >> 32));
        g_mstar_idx = (int)(unsigned)(g_minkey[sidx] & 0xFFFFFFFFull);
    }
}

__global__ void k_prep(const float* __restrict__ lib) {
    __shared__ float part[12];
    int t = threadIdx.x;
    int lane = t & 31, w = t >> 5;
    float mv = lib[(size_t)g_mstar_idx * DIM + t];
    g_mstar[t] = mv;
    g_mtest[t] = g_patch_n[g_sidx * DIM + t];
    float s = mv * mv;
#pragma unroll
    for (int o = 16; o > 0; o >>= 1) s += __shfl_down_sync(0xffffffffu, s, o);
    if (lane == 0) part[w] = s;
    __syncthreads();
    if (t == 0) { float tot = 0.f; for (int q = 0; q < 12; q++) tot += part[q]; g_msn = tot; }
}

__global__ void k_dstar(const float* __restrict__ lib) {
    int w = (blockIdx.x * blockDim.x + threadIdx.x) >> 5;
    int lane = threadIdx.x & 31;
    if (w >= M_LIB) return;
    const float* row = lib + (size_t)w * DIM;
    float s = 0.f;
#pragma unroll
    for (int i = 0; i < DIM / 32; i++) s += row[lane + 32 * i] * g_mstar[lane + 32 * i];
#pragma unroll
    for (int o = 16; o > 0; o >>= 1) s += __shfl_down_sync(0xffffffffu, s, o);
    if (lane == 0) {
        float d2 = g_ln[w] + g_msn - 2.0f * s;
        g_dstar[w] = sqrtf(fmaxf(d2, 0.f));
    }
}

__global__ void k_top5() {
    __shared__ ull s5[1024 * 5];
    int t = threadIdx.x;
    ull loc[5] = {~0ull, ~0ull, ~0ull, ~0ull, ~0ull};
    for (int m = t; m < M_LIB; m += 1024) {
        ull key = ((ull)__float_as_uint(g_dstar[m]) << 32) | (unsigned)m;
        if (key < loc[4]) {
            int p = 4;
            while (p > 0 && key < loc[p - 1]) { loc[p] = loc[p - 1]; p--; }
            loc[p] = key;
        }
    }
#pragma unroll
    for (int q = 0; q < 5; q++) s5[t * 5 + q] = loc[q];
    for (int off = 512; off >= 1; off >>= 1) {
        __syncthreads();
        if (t < off) {
            ull a[5], b[5], r[5];
#pragma unroll
            for (int q = 0; q < 5; q++) { a[q] = s5[t * 5 + q]; b[q] = s5[(t + off) * 5 + q]; }
            int i = 0, j = 0;
#pragma unroll
            for (int q = 0; q < 5; q++) r[q] = (a[i] <= b[j]) ? a[i++] : b[j++];
#pragma unroll
            for (int q = 0; q < 5; q++) s5[t * 5 + q] = r[q];
        }
    }
    __syncthreads();
    if (t == 0) for (int q = 0; q < 5; q++) g_top5[q] = s5[q];
}

__global__ void k_score(const float* __restrict__ lib, float* __restrict__ out) {
    __shared__ float nbsq[6];
    int t = threadIdx.x;
    int w = t >> 5, lane = t & 31;
    const float* vec;
    if (w < 5) vec = lib + (size_t)(unsigned)(g_top5[w] & 0xFFFFFFFFull) * DIM;
    else       vec = g_mstar;
    float s = 0.f;
#pragma unroll
    for (int i = 0; i < DIM / 32; i++) {
        float d = g_mtest[lane + 32 * i] - vec[lane + 32 * i];
        s += d * d;
    }
#pragma unroll
    for (int o = 16; o > 0; o >>= 1) s += __shfl_down_sync(0xffffffffu, s, o);
    if (lane == 0) nbsq[w] = s;
    __syncthreads();
    if (t == 0) {
        float denom = 0.f;
        for (int q = 0; q < 5; q++) denom += expf(sqrtf(nbsq[q]));
        float numer = expf(sqrtf(nbsq[5]));
        out[0] = (1.0f - numer / denom) * g_sstar;
    }
}

// ---------------- resize + blur ----------------
__global__ void k_resize() {
    int idx = blockIdx.x * blockDim.x + threadIdx.x;
    if (idx >= IMG * IMG) return;
    int x = idx % IMG, y = idx / IMG;
    const float sc = 26.0f / 224.0f;
    float sx = (x + 0.5f) * sc - 0.5f;
    float sy = (y + 0.5f) * sc - 0.5f;
    int x0 = (int)floorf(sx), y0 = (int)floorf(sy);
    float wx = sx - (float)x0, wy = sy - (float)y0;
    int x0c = min(max(x0, 0), 25), x1c = min(max(x0 + 1, 0), 25);
    int y0c = min(max(y0, 0), 25), y1c = min(max(y0 + 1, 0), 25);
    float v00 = g_map26[y0c * 26 + x0c], v01 = g_map26[y0c * 26 + x1c];
    float v10 = g_map26[y1c * 26 + x0c], v11 = g_map26[y1c * 26 + x1c];
    g_resized[idx] = (1.f - wy) * ((1.f - wx) * v00 + wx * v01) + wy * ((1.f - wx) * v10 + wx * v11);
}

__device__ __forceinline__ int reflect_(int i) {
    if (i < 0) return -i;
    if (i >= IMG) return 2 * IMG - 2 - i;
    return i;
}

__global__ void k_blur_v() {
    int idx = blockIdx.x * blockDim.x + threadIdx.x;
    if (idx >= IMG * IMG) return;
    int x = idx % IMG, y = idx / IMG;
    float s = 0.f;
#pragma unroll
    for (int t = 0; t < KS; t++) { int yy = reflect_(y + t - RAD); s += g_gw[t] * g_resized[yy * IMG + x]; }
    g_tmp[idx] = s;
}

__global__ void k_blur_h(float* __restrict__ out) {
    int idx = blockIdx.x * blockDim.x + threadIdx.x;
    if (idx >= IMG * IMG) return;
    int x = idx % IMG, y = idx / IMG;
    float s = 0.f;
#pragma unroll
    for (int t = 0; t < KS; t++) { int xx = reflect_(x + t - RAD); s += g_gw[t] * g_tmp[y * IMG + xx]; }
    out[1 + idx] = s;
}

// ---------------- launch ----------------
extern "C" void kernel_launch(void* const* d_in, const int* in_sizes, int n_in,
                              void* d_out, int out_size) {
    const float* patch = (const float*)d_in[0];
    const float* lib   = (const float*)d_in[1];
    if (n_in >= 2 && in_sizes[0] > in_sizes[1]) {
        const float* t = patch; patch = lib; lib = t;
    }
    float* out = (float*)d_out;

    cudaFuncSetAttribute(k_gemm_mma, cudaFuncAttributeMaxDynamicSharedMemorySize, SMEM_TOTAL_B);

    k_init<<<1, 256>>>();
    k_normalize<<<N_PATCH, 128>>>(patch);
    k_split_ln<<<(M_LIB * 32 + 255) / 256, 256>>>(lib);

    dim3 grid(NT_PATCH, NT_LIB);   // patch tiles fastest -> lib tile L2 reuse
    k_gemm_mma<<<grid, 256, SMEM_TOTAL_B>>>();

    k_argmax<<<1, 1024>>>();
    k_prep<<<1, DIM>>>(lib);
    k_dstar<<<(M_LIB * 32 + 255) / 256, 256>>>(lib);
    k_top5<<<1, 1024>>>();
    k_score<<<1, 192>>>(lib, out);

    int px = IMG * IMG;
    k_resize<<<(px + 255) / 256, 256>>>();
    k_blur_v<<<(px + 255) / 256, 256>>>();
    k_blur_h<<<(px + 255) / 256, 256>>>(out);
}